// round 5
// baseline (speedup 1.0000x reference)
#include <cuda_runtime.h>
#include <cstdint>

// Problem constants
#define C_IN   128
#define D_OUT  256
#define IMG    64
#define R1     8
#define R2     4
#define KC     32          // input channels per K-chunk
#define NIT    36          // 4 c-chunks * 9 taps
#define TH     2           // output rows per CTA (M = 2*64 = 128)

// SMEM word-layout (32-bit words)
#define SLAB_POS     264               // 4 rows * 66 cols
#define SLAB_STRIDE  33                // 32 permuted channels + 1 pad
#define SLAB_WORDS   (SLAB_POS * SLAB_STRIDE)      // 8712
#define SLAB_ELEMS   (KC * SLAB_POS)               // 8448
#define B_STRIDE     36                // 32 c + 4 pad (16B-aligned rows, conflict-free frags)
#define B_PAIR_WORDS (64 * B_STRIDE)               // 2304 words = one pair buffer
#define SM_B         (2 * SLAB_WORDS)              // after the two slab buffers
#define SM_TOTALW    (SM_B + 8 * B_PAIR_WORDS)     // 17424 + 18432 = 35856 w = 143424 B

// Reconstructed weights (tf32-rounded), laid out [tap][d][c] (c contiguous)
__device__ float g_Wtap[9 * D_OUT * C_IN];

__device__ __forceinline__ uint32_t f2tf32(float f) {
    uint32_t r;
    asm("cvt.rna.tf32.f32 %0, %1;" : "=r"(r) : "f"(f));
    return r;
}
__device__ __forceinline__ void mma_tf32(float* d, const uint32_t* a, const uint32_t* b) {
    asm volatile(
        "mma.sync.aligned.m16n8k8.row.col.f32.tf32.tf32.f32 "
        "{%0,%1,%2,%3}, {%4,%5,%6,%7}, {%8,%9}, {%0,%1,%2,%3};"
        : "+f"(d[0]), "+f"(d[1]), "+f"(d[2]), "+f"(d[3])
        : "r"(a[0]), "r"(a[1]), "r"(a[2]), "r"(a[3]), "r"(b[0]), "r"(b[1]));
}
__device__ __forceinline__ void cp_async16(uint32_t saddr, const void* gptr) {
    asm volatile("cp.async.ca.shared.global [%0], [%1], 16;" :: "r"(saddr), "l"(gptr));
}
__device__ __forceinline__ void bar_pair(int id) {
    asm volatile("bar.sync %0, 64;" :: "r"(id) : "memory");
}

// ---------------------------------------------------------------------------
// Phase 1: W[d,c,kh,kw] = sum_{r,s} core0[d,c,r]*core1[d,r,kh,s]*core2[d,s,kw]
// stored tf32-rounded as g_Wtap[tap][d][c]
// ---------------------------------------------------------------------------
__global__ void build_w_kernel(const float* __restrict__ core0,
                               const float* __restrict__ core1,
                               const float* __restrict__ core2) {
    const int d = blockIdx.x;
    const int t = threadIdx.x;           // 128
    __shared__ float M[R1 * 9];
    if (t < R1 * 9) {
        const int r = t / 9, kj = t % 9, kh = kj / 3, kw = kj % 3;
        float acc = 0.f;
        #pragma unroll
        for (int s = 0; s < R2; s++)
            acc += core1[((d * R1 + r) * 3 + kh) * R2 + s] * core2[(d * R2 + s) * 3 + kw];
        M[t] = acc;
    }
    __syncthreads();
    const int c = t;
    float a[R1];
    #pragma unroll
    for (int r = 0; r < R1; r++) a[r] = core0[(d * C_IN + c) * R1 + r];
    #pragma unroll
    for (int kj = 0; kj < 9; kj++) {
        float acc = 0.f;
        #pragma unroll
        for (int r = 0; r < R1; r++) acc += a[r] * M[r * 9 + kj];
        g_Wtap[(kj * D_OUT + d) * C_IN + c] = __uint_as_float(f2tf32(acc));
    }
}

// ---------------------------------------------------------------------------
// Phase 2: tf32 mma.sync implicit GEMM, pair-decoupled pipeline.
// CTA: M=128 (2 rows x 64 cols) x N=256. 8 warps = 2(M) x 4(N); warp 64x64.
// Warp PAIRS (wid 2p,2p+1) share warp_n=p: each pair double-buffers its own
// 64-d B slice via cp.async and syncs with bar.sync(id,64) only.
// Slab double-buffered; next chunk staged in slices during taps 0..7.
// Block barriers only at the 3 chunk flips.
// ---------------------------------------------------------------------------
__global__ __launch_bounds__(256, 1)
void conv_mma_kernel(const float* __restrict__ x,
                     const float* __restrict__ bias,
                     float* __restrict__ out) {
    extern __shared__ uint32_t smw[];
    const int tid = threadIdx.x;
    const int wid = tid >> 5;
    const int lane = tid & 31;
    const int g = lane >> 2;
    const int q = lane & 3;
    const int warp_m = wid & 1;
    const int warp_n = wid >> 1;              // == pair id
    const int tid64 = tid & 63;               // thread within pair
    const int n  = blockIdx.y;
    const int h0 = blockIdx.x * TH;

    uint32_t smem_base;
    asm("{ .reg .u64 t; cvta.to.shared.u64 t, %1; cvt.u32.u64 %0, t; }"
        : "=r"(smem_base) : "l"((void*)smw));

    float acc[4][8][4];
    #pragma unroll
    for (int i = 0; i < 4; i++)
        #pragma unroll
        for (int j = 0; j < 8; j++)
            #pragma unroll
            for (int k = 0; k < 4; k++) acc[i][j][k] = 0.f;

    // ---- helpers ----
    auto slab_store = [&](uint32_t* sl, int c0, int idx) {
        const int c   = idx / SLAB_POS;
        const int pos = idx % SLAB_POS;
        const int r   = pos / 66;
        const int col = pos % 66;
        const int h_in = h0 - 1 + r;
        const int w_in = col - 1;
        float v = 0.f;
        if ((unsigned)h_in < (unsigned)IMG && (unsigned)w_in < (unsigned)IMG)
            v = x[((n * C_IN + c0 + c) * IMG + h_in) * IMG + w_in];
        const int cp = (c & 3) * 8 + (c >> 2);        // permute for conflict-free frags
        sl[pos * SLAB_STRIDE + cp] = f2tf32(v);
    };
    auto issue_B = [&](int it, int buf) {
        const int c0  = (it / 9) * KC;
        const int tap = it % 9;
        const uint32_t sbase = smem_base +
            (SM_B + (warp_n * 2 + buf) * B_PAIR_WORDS) * 4;
        const float* gbase = g_Wtap + ((size_t)tap * D_OUT + warp_n * 64) * C_IN + c0;
        #pragma unroll
        for (int t = 0; t < 8; t++) {
            const int i4 = tid64 + t * 64;            // 0..511
            const int dd = i4 >> 3;                   // local d 0..63
            const int c4 = i4 & 7;                    // 16B chunk in c
            cp_async16(sbase + (dd * B_STRIDE + c4 * 4) * 4,
                       gbase + dd * C_IN + c4 * 4);
        }
        asm volatile("cp.async.commit_group;" ::: "memory");
    };

    // ---- prologue: B(0) + full slab(chunk 0) ----
    issue_B(0, 0);
    for (int idx = tid; idx < SLAB_ELEMS; idx += 256) slab_store(smw, 0, idx);
    __syncthreads();

    const int barid = 1 + warp_n;

    for (int it = 0; it < NIT; it++) {
        const int cc  = it / 9;
        const int tap = it % 9;
        const int kh = tap / 3, kw = tap % 3;
        const uint32_t* const slab = smw + (cc & 1) * SLAB_WORDS;
        const uint32_t* const B = smw + SM_B + (warp_n * 2 + (it & 1)) * B_PAIR_WORDS;

        // pair barrier A: partner done reading the buffer we're about to refill
        if (it > 0) bar_pair(barid);
        if (it + 1 < NIT) {
            issue_B(it + 1, (it + 1) & 1);
            asm volatile("cp.async.wait_group 1;" ::: "memory");
        } else {
            asm volatile("cp.async.wait_group 0;" ::: "memory");
        }
        // pair barrier B: partner's half of B(it) is complete
        bar_pair(barid);

        // ---- MMA: 4 ksteps of K=8 ----
        const int posA = (warp_m + kh) * 66 + g + kw;
        #pragma unroll
        for (int ks = 0; ks < 4; ks++) {
            uint32_t a[4][4];
            #pragma unroll
            for (int i = 0; i < 4; i++) {
                const int w0 = (posA + i * 16) * SLAB_STRIDE + q * 8 + ks * 2;
                a[i][0] = slab[w0];
                a[i][2] = slab[w0 + 1];
                const int w1 = w0 + 8 * SLAB_STRIDE;
                a[i][1] = slab[w1];
                a[i][3] = slab[w1 + 1];
            }
            uint32_t b[8][2];
            #pragma unroll
            for (int j = 0; j < 8; j++) {
                const int w0 = (j * 8 + g) * B_STRIDE + ks * 8 + q;
                b[j][0] = B[w0];
                b[j][1] = B[w0 + 4];
            }
            #pragma unroll
            for (int i = 0; i < 4; i++)
                #pragma unroll
                for (int j = 0; j < 8; j++)
                    mma_tf32(acc[i][j], a[i], b[j]);
        }

        // ---- distributed slab staging for next chunk (taps 0..7) ----
        if (cc < 3) {
            uint32_t* const nslab = smw + ((cc + 1) & 1) * SLAB_WORDS;
            if (tap < 8) {
                const int base = tap * 1056;
                for (int idx = base + tid; idx < base + 1056; idx += 256)
                    slab_store(nslab, (cc + 1) * KC, idx);
            } else {
                __syncthreads();    // flip slab buffers (3 times total)
            }
        }
    }

    // ---- epilogue: acc -> out[n][d][h][w] + bias ----
    const float bval = bias[0];
    const int h = h0 + warp_m;
    #pragma unroll
    for (int i = 0; i < 4; i++) {
        const int w0 = i * 16 + g;
        #pragma unroll
        for (int j = 0; j < 8; j++) {
            const int d = warp_n * 64 + j * 8 + 2 * q;
            float* p0 = out + (((size_t)n * D_OUT + d) * IMG + h) * IMG;
            float* p1 = p0 + (size_t)IMG * IMG;
            p0[w0]     = acc[i][j][0] + bval;
            p1[w0]     = acc[i][j][1] + bval;
            p0[w0 + 8] = acc[i][j][2] + bval;
            p1[w0 + 8] = acc[i][j][3] + bval;
        }
    }
}

// ---------------------------------------------------------------------------
// Inputs (metadata order): x, core0, core1, core2, bias, [stride, pad]
// ---------------------------------------------------------------------------
extern "C" void kernel_launch(void* const* d_in, const int* in_sizes, int n_in,
                              void* d_out, int out_size) {
    const float* x     = (const float*)d_in[0];
    const float* core0 = (const float*)d_in[1];
    const float* core1 = (const float*)d_in[2];
    const float* core2 = (const float*)d_in[3];
    const float* bias  = (const float*)d_in[4];
    float* out = (float*)d_out;

    build_w_kernel<<<D_OUT, C_IN>>>(core0, core1, core2);

    const int smem_bytes = SM_TOTALW * 4;
    cudaFuncSetAttribute(conv_mma_kernel, cudaFuncAttributeMaxDynamicSharedMemorySize, smem_bytes);
    conv_mma_kernel<<<dim3(IMG / TH, 32), 256, smem_bytes>>>(x, bias, out);
}

// round 6
// speedup vs baseline: 1.2720x; 1.2720x over previous
#include <cuda_runtime.h>
#include <cstdint>

// Problem constants
#define C_IN   128
#define D_OUT  256
#define IMG    64
#define R1     8
#define R2     4
#define KC     32          // input channels per K-chunk
#define NIT    36          // 4 c-chunks * 9 taps
#define TH     2           // output rows per CTA (M = 2*64 = 128)
#define ND     128         // output channels per CTA (N tile)

// SMEM word-layout (32-bit words)
#define SLAB_POS     264               // 4 rows * 66 cols
#define SLAB_STRIDE  33                // 32 permuted channels + 1 pad
#define SLAB_WORDS   (SLAB_POS * SLAB_STRIDE)      // 8712
#define SLAB_ELEMS   (KC * SLAB_POS)               // 8448
#define B_STRIDE     136               // 128 d + 8 pad (bank = 8q+g, conflict-free)
#define B_WORDS      (KC * B_STRIDE)               // 4352
#define SM_B         SLAB_WORDS
#define SM_TOTALW    (SM_B + 2 * B_WORDS)          // 17416 words = 69664 B

// Reconstructed weights (tf32-rounded), laid out [tap][c][d]
__device__ float g_Wtap[9 * C_IN * D_OUT];

__device__ __forceinline__ uint32_t f2tf32(float f) {
    uint32_t r;
    asm("cvt.rna.tf32.f32 %0, %1;" : "=r"(r) : "f"(f));
    return r;
}
__device__ __forceinline__ void mma_tf32(float* d, const uint32_t* a, const uint32_t* b) {
    asm volatile(
        "mma.sync.aligned.m16n8k8.row.col.f32.tf32.tf32.f32 "
        "{%0,%1,%2,%3}, {%4,%5,%6,%7}, {%8,%9}, {%0,%1,%2,%3};"
        : "+f"(d[0]), "+f"(d[1]), "+f"(d[2]), "+f"(d[3])
        : "r"(a[0]), "r"(a[1]), "r"(a[2]), "r"(a[3]), "r"(b[0]), "r"(b[1]));
}
__device__ __forceinline__ void cp_async16(uint32_t saddr, const void* gptr) {
    asm volatile("cp.async.ca.shared.global [%0], [%1], 16;" :: "r"(saddr), "l"(gptr));
}

// ---------------------------------------------------------------------------
// Phase 1: W[d,c,kh,kw] = sum_{r,s} core0[d,c,r]*core1[d,r,kh,s]*core2[d,s,kw]
// stored tf32-rounded as g_Wtap[tap][c][d]
// ---------------------------------------------------------------------------
__global__ void build_w_kernel(const float* __restrict__ core0,
                               const float* __restrict__ core1,
                               const float* __restrict__ core2) {
    const int d = blockIdx.x;
    const int t = threadIdx.x;           // 128
    __shared__ float M[R1 * 9];
    if (t < R1 * 9) {
        const int r = t / 9, kj = t % 9, kh = kj / 3, kw = kj % 3;
        float acc = 0.f;
        #pragma unroll
        for (int s = 0; s < R2; s++)
            acc += core1[((d * R1 + r) * 3 + kh) * R2 + s] * core2[(d * R2 + s) * 3 + kw];
        M[t] = acc;
    }
    __syncthreads();
    const int c = t;
    float a[R1];
    #pragma unroll
    for (int r = 0; r < R1; r++) a[r] = core0[(d * C_IN + c) * R1 + r];
    #pragma unroll
    for (int kj = 0; kj < 9; kj++) {
        float acc = 0.f;
        #pragma unroll
        for (int r = 0; r < R1; r++) acc += a[r] * M[r * 9 + kj];
        g_Wtap[(kj * C_IN + c) * D_OUT + d] = __uint_as_float(f2tf32(acc));
    }
}

// ---------------------------------------------------------------------------
// Phase 2: tf32 mma.sync implicit GEMM (R3 pipeline, half-N CTA for 2 CTA/SM).
// CTA: M=128 (2 rows x 64 cols) x N=128. 8 warps = 2(M-row) x 4(N); warp 64x32.
// K loop: 4 c-chunks x 9 taps x 4 ksteps(K=8).  B double-buffered via cp.async.
// ---------------------------------------------------------------------------
__global__ __launch_bounds__(256, 2)
void conv_mma_kernel(const float* __restrict__ x,
                     const float* __restrict__ bias,
                     float* __restrict__ out) {
    extern __shared__ uint32_t smw[];
    uint32_t* const slab = smw;
    const int tid = threadIdx.x;
    const int wid = tid >> 5;
    const int lane = tid & 31;
    const int g = lane >> 2;
    const int q = lane & 3;
    const int warp_m = wid & 1;               // output row within tile
    const int warp_n = wid >> 1;              // 0..3 (32-d slice)
    const int ny = blockIdx.y;                // 0..1 N-half
    const int n  = blockIdx.z;
    const int h0 = blockIdx.x * TH;

    uint32_t smem_base;
    asm("{ .reg .u64 t; cvta.to.shared.u64 t, %1; cvt.u32.u64 %0, t; }"
        : "=r"(smem_base) : "l"((void*)smw));

    float acc[4][4][4];
    #pragma unroll
    for (int i = 0; i < 4; i++)
        #pragma unroll
        for (int j = 0; j < 4; j++)
            #pragma unroll
            for (int k = 0; k < 4; k++) acc[i][j][k] = 0.f;

    // ---- staging helpers ----
    auto stage_slab = [&](int c0) {
        for (int idx = tid; idx < SLAB_ELEMS; idx += 256) {
            const int c   = idx / SLAB_POS;
            const int pos = idx % SLAB_POS;
            const int r   = pos / 66;
            const int col = pos % 66;
            const int h_in = h0 - 1 + r;
            const int w_in = col - 1;
            float v = 0.f;
            if ((unsigned)h_in < (unsigned)IMG && (unsigned)w_in < (unsigned)IMG)
                v = x[((n * C_IN + c0 + c) * IMG + h_in) * IMG + w_in];
            const int cp = (c & 3) * 8 + (c >> 2);
            slab[pos * SLAB_STRIDE + cp] = f2tf32(v);
        }
    };
    auto issue_B = [&](int it, int buf) {
        const int c0  = (it / 9) * KC;
        const int tap = it % 9;
        const uint32_t sbase = smem_base + (SM_B + buf * B_WORDS) * 4;
        const float* gbase = g_Wtap + (size_t)tap * C_IN * D_OUT + ny * ND;
        #pragma unroll
        for (int t = 0; t < 4; t++) {
            const int i4 = tid + t * 256;       // 0..1023 float4s
            const int c  = i4 >> 5;             // 0..31
            const int d4 = i4 & 31;             // 0..31 (128 d / 4)
            cp_async16(sbase + (c * B_STRIDE + d4 * 4) * 4,
                       gbase + (size_t)(c0 + c) * D_OUT + d4 * 4);
        }
        asm volatile("cp.async.commit_group;" ::: "memory");
    };

    // ---- prologue ----
    issue_B(0, 0);
    stage_slab(0);

    for (int it = 0; it < NIT; it++) {
        const int tap = it % 9;
        const int kh = tap / 3, kw = tap % 3;
        const uint32_t* const B = smw + SM_B + (it & 1) * B_WORDS;

        if (it + 1 < NIT) {
            issue_B(it + 1, (it + 1) & 1);
            asm volatile("cp.async.wait_group 1;" ::: "memory");
        } else {
            asm volatile("cp.async.wait_group 0;" ::: "memory");
        }
        __syncthreads();
        if (it > 0 && tap == 0) {
            stage_slab((it / 9) * KC);
            __syncthreads();
        }

        // ---- 4 ksteps of K=8 ----
        const int posA = (warp_m + kh) * 66 + g + kw;
        #pragma unroll
        for (int ks = 0; ks < 4; ks++) {
            uint32_t a[4][4];
            #pragma unroll
            for (int i = 0; i < 4; i++) {
                const int w0 = (posA + i * 16) * SLAB_STRIDE + q * 8 + ks * 2;
                a[i][0] = slab[w0];
                a[i][2] = slab[w0 + 1];
                const int w1 = w0 + 8 * SLAB_STRIDE;
                a[i][1] = slab[w1];
                a[i][3] = slab[w1 + 1];
            }
            uint32_t b[4][2];
            #pragma unroll
            for (int j = 0; j < 4; j++) {
                const int w0 = (ks * 8 + q) * B_STRIDE + warp_n * 32 + j * 8 + g;
                b[j][0] = B[w0];
                b[j][1] = B[w0 + 4 * B_STRIDE];
            }
            #pragma unroll
            for (int i = 0; i < 4; i++)
                #pragma unroll
                for (int j = 0; j < 4; j++)
                    mma_tf32(acc[i][j], a[i], b[j]);
        }
        __syncthreads();   // B buffer reuse + slab overwrite protection
    }

    // ---- epilogue: acc -> out[n][d][h][w] + bias ----
    const float bval = bias[0];
    const int h = h0 + warp_m;
    #pragma unroll
    for (int i = 0; i < 4; i++) {
        const int w0 = i * 16 + g;
        #pragma unroll
        for (int j = 0; j < 4; j++) {
            const int d = ny * ND + warp_n * 32 + j * 8 + 2 * q;
            float* p0 = out + (((size_t)n * D_OUT + d) * IMG + h) * IMG;
            float* p1 = p0 + (size_t)IMG * IMG;       // d+1
            p0[w0]     = acc[i][j][0] + bval;
            p1[w0]     = acc[i][j][1] + bval;
            p0[w0 + 8] = acc[i][j][2] + bval;
            p1[w0 + 8] = acc[i][j][3] + bval;
        }
    }
}

// ---------------------------------------------------------------------------
// Inputs (metadata order): x, core0, core1, core2, bias, [stride, pad]
// ---------------------------------------------------------------------------
extern "C" void kernel_launch(void* const* d_in, const int* in_sizes, int n_in,
                              void* d_out, int out_size) {
    const float* x     = (const float*)d_in[0];
    const float* core0 = (const float*)d_in[1];
    const float* core1 = (const float*)d_in[2];
    const float* core2 = (const float*)d_in[3];
    const float* bias  = (const float*)d_in[4];
    float* out = (float*)d_out;

    build_w_kernel<<<D_OUT, C_IN>>>(core0, core1, core2);

    const int smem_bytes = SM_TOTALW * 4;
    cudaFuncSetAttribute(conv_mma_kernel, cudaFuncAttributeMaxDynamicSharedMemorySize, smem_bytes);
    conv_mma_kernel<<<dim3(IMG / TH, 2, 32), 256, smem_bytes>>>(x, bias, out);
}

// round 7
// speedup vs baseline: 1.3159x; 1.0345x over previous
#include <cuda_runtime.h>
#include <cstdint>

// Problem constants
#define C_IN   128
#define D_OUT  256
#define IMG    64
#define R1     8
#define R2     4
#define KC     32          // input channels per K-chunk
#define NIT    36          // 4 c-chunks * 9 taps
#define TH     2           // output rows per CTA (M = 2*64 = 128)
#define ND     128         // output channels per CTA (N tile)

// SMEM word-layout (32-bit words)
#define SLAB_POS     264               // 4 rows * 66 cols
#define SLAB_STRIDE  34                // 32 permuted channels + 2 pad (even: 8B-aligned pairs)
#define SLAB_WORDS   (SLAB_POS * SLAB_STRIDE)      // 8976
#define SLAB_ELEMS   (KC * SLAB_POS)               // 8448
#define B_STRIDE     264               // 128 d * 2 pair-words + 8 pad (bank = 8q+2g)
#define B_WORDS      (16 * B_STRIDE)               // 4224 (16 k-pair rows)
#define SM_B         SLAB_WORDS
#define SM_TOTALW    (SM_B + 3 * B_WORDS)          // 21648 words = 86592 B

// Reconstructed weights (tf32), k-pair interleaved:
// g_Wp[((tap*4+cc)*16 + ks*4+q)*512 + d*2 + u]  where channel c = cc*32+ks*8+q+4u
__device__ float g_Wp[9 * 4 * 16 * 512];

__device__ __forceinline__ uint32_t f2tf32(float f) {
    uint32_t r;
    asm("cvt.rna.tf32.f32 %0, %1;" : "=r"(r) : "f"(f));
    return r;
}
__device__ __forceinline__ void mma_tf32(float* d, const uint32_t* a, const uint32_t* b) {
    asm volatile(
        "mma.sync.aligned.m16n8k8.row.col.f32.tf32.tf32.f32 "
        "{%0,%1,%2,%3}, {%4,%5,%6,%7}, {%8,%9}, {%0,%1,%2,%3};"
        : "+f"(d[0]), "+f"(d[1]), "+f"(d[2]), "+f"(d[3])
        : "r"(a[0]), "r"(a[1]), "r"(a[2]), "r"(a[3]), "r"(b[0]), "r"(b[1]));
}
__device__ __forceinline__ void cp_async16(uint32_t saddr, const void* gptr) {
    asm volatile("cp.async.ca.shared.global [%0], [%1], 16;" :: "r"(saddr), "l"(gptr));
}

// ---------------------------------------------------------------------------
// Phase 1: W[d,c,kh,kw] = sum_{r,s} core0[d,c,r]*core1[d,r,kh,s]*core2[d,s,kw]
// stored tf32-rounded in the k-pair interleaved layout above.
// ---------------------------------------------------------------------------
__global__ void build_w_kernel(const float* __restrict__ core0,
                               const float* __restrict__ core1,
                               const float* __restrict__ core2) {
    const int d = blockIdx.x;
    const int t = threadIdx.x;           // 128
    __shared__ float M[R1 * 9];
    if (t < R1 * 9) {
        const int r = t / 9, kj = t % 9, kh = kj / 3, kw = kj % 3;
        float acc = 0.f;
        #pragma unroll
        for (int s = 0; s < R2; s++)
            acc += core1[((d * R1 + r) * 3 + kh) * R2 + s] * core2[(d * R2 + s) * 3 + kw];
        M[t] = acc;
    }
    __syncthreads();
    const int c = t;
    const int cc = c >> 5, cl = c & 31;
    const int ks = cl >> 3, kk = cl & 7;
    const int q = kk & 3, u = kk >> 2;
    float a[R1];
    #pragma unroll
    for (int r = 0; r < R1; r++) a[r] = core0[(d * C_IN + c) * R1 + r];
    #pragma unroll
    for (int kj = 0; kj < 9; kj++) {
        float acc = 0.f;
        #pragma unroll
        for (int r = 0; r < R1; r++) acc += a[r] * M[r * 9 + kj];
        g_Wp[(((kj * 4 + cc) * 16) + ks * 4 + q) * 512 + d * 2 + u] =
            __uint_as_float(f2tf32(acc));
    }
}

// ---------------------------------------------------------------------------
// Phase 2: tf32 mma.sync implicit GEMM.
// CTA: M=128 (2 rows x 64 cols) x N=128. 8 warps = 2(M-row) x 4(N); warp 64x32.
// K loop: 4 c-chunks x 9 taps x 4 ksteps(K=8).
// B triple-buffered via cp.async (one block barrier per tap).
// All fragment loads are 64-bit, bank-conflict-free.
// ---------------------------------------------------------------------------
__global__ __launch_bounds__(256, 2)
void conv_mma_kernel(const float* __restrict__ x,
                     const float* __restrict__ bias,
                     float* __restrict__ out) {
    extern __shared__ uint32_t smw[];
    uint32_t* const slab = smw;
    const int tid = threadIdx.x;
    const int wid = tid >> 5;
    const int lane = tid & 31;
    const int g = lane >> 2;
    const int q = lane & 3;
    const int warp_m = wid & 1;               // output row within tile
    const int warp_n = wid >> 1;              // 0..3 (32-d slice)
    const int ny = blockIdx.y;                // 0..1 N-half
    const int n  = blockIdx.z;
    const int h0 = blockIdx.x * TH;

    uint32_t smem_base;
    asm("{ .reg .u64 t; cvta.to.shared.u64 t, %1; cvt.u32.u64 %0, t; }"
        : "=r"(smem_base) : "l"((void*)smw));

    float acc[4][4][4];
    #pragma unroll
    for (int i = 0; i < 4; i++)
        #pragma unroll
        for (int j = 0; j < 4; j++)
            #pragma unroll
            for (int k = 0; k < 4; k++) acc[i][j][k] = 0.f;

    // ---- staging helpers ----
    auto stage_slab = [&](int c0) {
        for (int idx = tid; idx < SLAB_ELEMS; idx += 256) {
            const int c   = idx / SLAB_POS;
            const int pos = idx % SLAB_POS;
            const int r   = pos / 66;
            const int col = pos % 66;
            const int h_in = h0 - 1 + r;
            const int w_in = col - 1;
            float v = 0.f;
            if ((unsigned)h_in < (unsigned)IMG && (unsigned)w_in < (unsigned)IMG)
                v = x[((n * C_IN + c0 + c) * IMG + h_in) * IMG + w_in];
            const int cp = (c & 3) * 8 + (c >> 2);   // word cp = 8q+2ks+u, c=8ks+q+4u
            slab[pos * SLAB_STRIDE + cp] = f2tf32(v);
        }
    };
    auto issue_B = [&](int it, int buf) {
        const int cc  = it / 9;
        const int tap = it % 9;
        const uint32_t sbase = smem_base + (SM_B + buf * B_WORDS) * 4;
        const float* gbase = g_Wp + ((size_t)(tap * 4 + cc) * 16) * 512 + ny * 256;
        #pragma unroll
        for (int t = 0; t < 4; t++) {
            const int i4  = tid + t * 256;      // 0..1023 float4s
            const int row = i4 >> 6;            // k-pair row 0..15
            const int d4  = i4 & 63;            // 16B chunk
            cp_async16(sbase + (row * B_STRIDE + d4 * 4) * 4,
                       gbase + row * 512 + d4 * 4);
        }
        asm volatile("cp.async.commit_group;" ::: "memory");
    };

    // ---- prologue: B(0), B(1) in flight; slab chunk 0 ----
    issue_B(0, 0);
    issue_B(1, 1);
    stage_slab(0);

    for (int it = 0; it < NIT; it++) {
        const int cc  = it / 9;
        const int tap = it % 9;
        const int kh = tap / 3, kw = tap % 3;
        const uint32_t* const B = smw + SM_B + (it % 3) * B_WORDS;

        if (it == NIT - 1) { asm volatile("cp.async.wait_group 0;" ::: "memory"); }
        else               { asm volatile("cp.async.wait_group 1;" ::: "memory"); }
        __syncthreads();
        if (it > 0 && tap == 0) {
            stage_slab(cc * KC);
            __syncthreads();
        }
        if (it + 2 < NIT) issue_B(it + 2, (it + 2) % 3);
        else asm volatile("cp.async.commit_group;" ::: "memory");

        // ---- 4 ksteps of K=8, all-64-bit fragment loads ----
        const int posA = (warp_m + kh) * 66 + g + kw;
        #pragma unroll
        for (int ks = 0; ks < 4; ks++) {
            uint32_t a[4][4];
            #pragma unroll
            for (int i = 0; i < 4; i++) {
                const int w0 = (posA + i * 16) * SLAB_STRIDE + q * 8 + ks * 2;
                const uint2 lo = *(const uint2*)(slab + w0);
                const uint2 hi = *(const uint2*)(slab + w0 + 8 * SLAB_STRIDE);
                a[i][0] = lo.x; a[i][2] = lo.y;
                a[i][1] = hi.x; a[i][3] = hi.y;
            }
            uint32_t b[4][2];
            const uint32_t* Brow = B + (ks * 4 + q) * B_STRIDE + warp_n * 64 + g * 2;
            #pragma unroll
            for (int j = 0; j < 4; j++) {
                const uint2 bb = *(const uint2*)(Brow + j * 16);
                b[j][0] = bb.x; b[j][1] = bb.y;
            }
            #pragma unroll
            for (int i = 0; i < 4; i++)
                #pragma unroll
                for (int j = 0; j < 4; j++)
                    mma_tf32(acc[i][j], a[i], b[j]);
        }
    }

    // ---- epilogue: acc -> out[n][d][h][w] + bias ----
    const float bval = bias[0];
    const int h = h0 + warp_m;
    #pragma unroll
    for (int i = 0; i < 4; i++) {
        const int w0 = i * 16 + g;
        #pragma unroll
        for (int j = 0; j < 4; j++) {
            const int d = ny * ND + warp_n * 32 + j * 8 + 2 * q;
            float* p0 = out + (((size_t)n * D_OUT + d) * IMG + h) * IMG;
            float* p1 = p0 + (size_t)IMG * IMG;       // d+1
            p0[w0]     = acc[i][j][0] + bval;
            p1[w0]     = acc[i][j][1] + bval;
            p0[w0 + 8] = acc[i][j][2] + bval;
            p1[w0 + 8] = acc[i][j][3] + bval;
        }
    }
}

// ---------------------------------------------------------------------------
// Inputs (metadata order): x, core0, core1, core2, bias, [stride, pad]
// ---------------------------------------------------------------------------
extern "C" void kernel_launch(void* const* d_in, const int* in_sizes, int n_in,
                              void* d_out, int out_size) {
    const float* x     = (const float*)d_in[0];
    const float* core0 = (const float*)d_in[1];
    const float* core1 = (const float*)d_in[2];
    const float* core2 = (const float*)d_in[3];
    const float* bias  = (const float*)d_in[4];
    float* out = (float*)d_out;

    build_w_kernel<<<D_OUT, C_IN>>>(core0, core1, core2);

    const int smem_bytes = SM_TOTALW * 4;
    cudaFuncSetAttribute(conv_mma_kernel, cudaFuncAttributeMaxDynamicSharedMemorySize, smem_bytes);
    conv_mma_kernel<<<dim3(IMG / TH, 2, 32), 256, smem_bytes>>>(x, bias, out);
}

// round 8
// speedup vs baseline: 2.4977x; 1.8980x over previous
#include <cuda_runtime.h>
#include <cuda_fp16.h>
#include <cstdint>

// Problem constants
#define C_IN   128
#define D_OUT  256
#define IMG    64
#define R1     8
#define R2     4
#define KC     32          // input channels per K-chunk
#define NIT    36          // 4 c-chunks * 9 taps
#define TH     2           // output rows per CTA (M = 2*64 = 128)
#define ND     128         // output channels per CTA (N tile)

// SMEM word-layout (uint32 = half2 words)
#define SLAB_STRIDE  24                // 16 data words + 8 pad (LDS.64: 12g+q mod16 distinct)
#define SLAB_POS     264               // 4 rows * 66 cols (halo cols 0 and 65)
#define SLAB_WORDS   (SLAB_POS * SLAB_STRIDE)      // 6336
#define B_WORDS      2048              // 2 ks * 128 d * 8 words
#define SM_B         (2 * SLAB_WORDS)              // after double-buffered slab
#define SM_TOTALW    (SM_B + 3 * B_WORDS)          // 18816 words = 75264 B

// fp16 weights, fragment-ready: word idx = (((tap*4+cc)*2+ks)*256 + d)*8 + wB
//   channel c (even) -> ks=(c&31)>>4, c16=c&15, wB=(c16&7)+(c16>>3); half2=(W[c],W[c+1])
__device__ uint32_t g_Wp[9 * 4 * 2 * 256 * 8];
// fp16 x, fragment-ready: word idx = (((n*4+cc)*64+h)*64+w)*16 + sw
//   sw -> channels: ks=sw>>3, wl=sw&7, c = cc*32 + ks*16 + 2*(wl>>1) + 8*(wl&1), pair (c,c+1)
__device__ uint32_t g_xh[32 * 4 * 64 * 64 * 16];   // 33.5 MB

__device__ __forceinline__ void mma_f16(float* d, const uint32_t* a, const uint32_t* b) {
    asm volatile(
        "mma.sync.aligned.m16n8k16.row.col.f32.f16.f16.f32 "
        "{%0,%1,%2,%3}, {%4,%5,%6,%7}, {%8,%9}, {%0,%1,%2,%3};"
        : "+f"(d[0]), "+f"(d[1]), "+f"(d[2]), "+f"(d[3])
        : "r"(a[0]), "r"(a[1]), "r"(a[2]), "r"(a[3]), "r"(b[0]), "r"(b[1]));
}
__device__ __forceinline__ void cp_async16(uint32_t saddr, const void* gptr) {
    asm volatile("cp.async.ca.shared.global [%0], [%1], 16;" :: "r"(saddr), "l"(gptr));
}

// ---------------------------------------------------------------------------
// Phase 1a: rebuild W (tf32-free, full fp32 math), pack fp16 pairs into g_Wp
// ---------------------------------------------------------------------------
__global__ void build_w_kernel(const float* __restrict__ core0,
                               const float* __restrict__ core1,
                               const float* __restrict__ core2) {
    const int d = blockIdx.x;
    const int t = threadIdx.x;           // 128 threads = channels
    __shared__ float M[R1 * 9];
    if (t < R1 * 9) {
        const int r = t / 9, kj = t % 9, kh = kj / 3, kw = kj % 3;
        float acc = 0.f;
        #pragma unroll
        for (int s = 0; s < R2; s++)
            acc += core1[((d * R1 + r) * 3 + kh) * R2 + s] * core2[(d * R2 + s) * 3 + kw];
        M[t] = acc;
    }
    __syncthreads();
    const int c = t;
    float a[R1];
    #pragma unroll
    for (int r = 0; r < R1; r++) a[r] = core0[(d * C_IN + c) * R1 + r];
    #pragma unroll
    for (int kj = 0; kj < 9; kj++) {
        float acc = 0.f;
        #pragma unroll
        for (int r = 0; r < R1; r++) acc += a[r] * M[r * 9 + kj];
        const float hiv = __shfl_down_sync(0xffffffffu, acc, 1);
        if (!(c & 1)) {
            const int cc = c >> 5, cl = c & 31;
            const int ks = cl >> 4, c16 = cl & 15;
            const int wB = (c16 & 7) + (c16 >> 3);
            __half2 h2 = __floats2half2_rn(acc, hiv);
            g_Wp[((((kj * 4 + cc) * 2 + ks) * 256) + d) * 8 + wB] =
                *reinterpret_cast<uint32_t*>(&h2);
        }
    }
}

// ---------------------------------------------------------------------------
// Phase 1b: convert x -> fp16 fragment-ready layout g_xh
// block = (n*4+cc, h); 256 threads.
// ---------------------------------------------------------------------------
__global__ __launch_bounds__(256)
void prepack_x_kernel(const float* __restrict__ x) {
    const int ncc = blockIdx.x;          // n*4+cc
    const int h   = blockIdx.y;
    const int n   = ncc >> 2;
    const int cc  = ncc & 3;
    const int tid = threadIdx.x;
    __shared__ float xs[32][65];

    // coalesced load: 32 channels x 64 cols
    for (int i = tid; i < 32 * 64; i += 256) {
        const int c = i >> 6, w = i & 63;
        xs[c][w] = x[((n * C_IN + cc * 32 + c) * IMG + h) * IMG + w];
    }
    __syncthreads();

    // coalesced store of permuted half2 words
    uint32_t* dst = g_xh + ((size_t)(ncc * 64 + h) * 64) * 16;
    for (int i = tid; i < 64 * 16; i += 256) {
        const int w = i >> 4, sw = i & 15;
        const int ks = sw >> 3, wl = sw & 7;
        const int c = ks * 16 + 2 * (wl >> 1) + 8 * (wl & 1);
        __half2 h2 = __floats2half2_rn(xs[c][w], xs[c + 1][w]);
        dst[w * 16 + sw] = *reinterpret_cast<uint32_t*>(&h2);
    }
}

// ---------------------------------------------------------------------------
// Phase 2: fp16 m16n8k16 implicit GEMM.
// CTA: M=128 (2 rows x 64 cols) x N=128. 8 warps = 2(M-row) x 4(N); warp 64x32.
// K loop: 4 c-chunks x 9 taps x 2 ksteps(K=16).
// Slab double-buffered + B triple-buffered, all staging via cp.async.
// ---------------------------------------------------------------------------
__global__ __launch_bounds__(256, 2)
void conv_mma_kernel(const float* __restrict__ bias, float* __restrict__ out) {
    extern __shared__ uint32_t smw[];
    const int tid = threadIdx.x;
    const int wid = tid >> 5;
    const int lane = tid & 31;
    const int g = lane >> 2;
    const int q = lane & 3;
    const int warp_m = wid & 1;
    const int warp_n = wid >> 1;
    const int ny = blockIdx.y;
    const int n  = blockIdx.z;
    const int h0 = blockIdx.x * TH;

    uint32_t smem_base;
    asm("{ .reg .u64 t; cvta.to.shared.u64 t, %1; cvt.u32.u64 %0, t; }"
        : "=r"(smem_base) : "l"((void*)smw));

    float acc[4][4][4];
    #pragma unroll
    for (int i = 0; i < 4; i++)
        #pragma unroll
        for (int j = 0; j < 4; j++)
            #pragma unroll
            for (int k = 0; k < 4; k++) acc[i][j][k] = 0.f;

    auto issue_slab = [&](int cc, int buf) {
        const uint32_t sbase = smem_base + buf * SLAB_WORDS * 4;
        const uint32_t* gsrc = g_xh + ((size_t)(n * 4 + cc) * 64) * 64 * 16;
        #pragma unroll
        for (int t = 0; t < 4; t++) {
            const int i = tid + t * 256;      // 0..1023
            const int r = i >> 8, rem = i & 255;
            const int w = rem >> 2, cq = rem & 3;
            const int h = h0 - 1 + r;
            if ((unsigned)h < (unsigned)IMG)
                cp_async16(sbase + (((r * 66 + 1 + w) * SLAB_STRIDE) + cq * 4) * 4,
                           gsrc + ((size_t)h * 64 + w) * 16 + cq * 4);
        }
    };
    auto issue_B = [&](int it) {
        const int cc = it / 9, tap = it % 9, buf = it % 3;
        const uint32_t sbase = smem_base + (SM_B + buf * B_WORDS) * 4;
        const uint32_t* gsrc = g_Wp + ((size_t)(tap * 4 + cc) * 2) * 2048 + ny * 1024;
        #pragma unroll
        for (int t = 0; t < 2; t++) {
            const int i = tid + t * 256;      // 0..511
            const int ks = i >> 8, ci = i & 255;
            cp_async16(sbase + (ks * 1024 + ci * 4) * 4, gsrc + ks * 2048 + ci * 4);
        }
    };

    // ---- prologue: zero both slab buffers (halo/OOB stays zero), then stage ----
    for (int i = tid; i < 2 * SLAB_WORDS; i += 256) smw[i] = 0;
    __syncthreads();
    issue_slab(0, 0);
    issue_B(0);
    asm volatile("cp.async.commit_group;" ::: "memory");
    issue_B(1);
    asm volatile("cp.async.commit_group;" ::: "memory");

    for (int it = 0; it < NIT; it++) {
        const int cc  = it / 9;
        const int tap = it % 9;
        const int kh = tap / 3, kw = tap % 3;
        const uint32_t* const slab = smw + (cc & 1) * SLAB_WORDS;
        const uint32_t* const B = smw + SM_B + (it % 3) * B_WORDS;

        if (it + 2 < NIT) issue_B(it + 2);
        if (tap == 4 && cc < 3) issue_slab(cc + 1, (cc + 1) & 1);
        asm volatile("cp.async.commit_group;" ::: "memory");
        asm volatile("cp.async.wait_group 1;" ::: "memory");
        __syncthreads();

        // slab col = wcol + kw (halo offset +1 built in); frag rows add g, +i*16, +8
        const int posA = (warp_m + kh) * 66 + kw + g;
        #pragma unroll
        for (int ks = 0; ks < 2; ks++) {
            uint32_t a[4][4];
            #pragma unroll
            for (int i = 0; i < 4; i++) {
                const int w0 = (posA + i * 16) * SLAB_STRIDE + ks * 8 + 2 * q;
                const uint2 lo = *(const uint2*)(slab + w0);
                const uint2 hi = *(const uint2*)(slab + w0 + 8 * SLAB_STRIDE);
                a[i][0] = lo.x; a[i][1] = hi.x;   // k 2q..2q+1, rows g / g+8
                a[i][2] = lo.y; a[i][3] = hi.y;   // k 2q+8..2q+9
            }
            uint32_t b[4][2];
            const uint32_t* Brow = B + ks * 1024 + (warp_n * 32 + g) * 8 + 2 * q;
            #pragma unroll
            for (int j = 0; j < 4; j++) {
                const uint2 bb = *(const uint2*)(Brow + j * 64);
                b[j][0] = bb.x; b[j][1] = bb.y;
            }
            #pragma unroll
            for (int i = 0; i < 4; i++)
                #pragma unroll
                for (int j = 0; j < 4; j++)
                    mma_f16(acc[i][j], a[i], b[j]);
        }
        __syncthreads();    // protect buffers being refilled next iter
    }

    // ---- epilogue: acc -> out[n][d][h][w] + bias ----
    const float bval = bias[0];
    const int h = h0 + warp_m;
    #pragma unroll
    for (int i = 0; i < 4; i++) {
        const int w0 = i * 16 + g;
        #pragma unroll
        for (int j = 0; j < 4; j++) {
            const int d = ny * ND + warp_n * 32 + j * 8 + 2 * q;
            float* p0 = out + (((size_t)n * D_OUT + d) * IMG + h) * IMG;
            float* p1 = p0 + (size_t)IMG * IMG;       // d+1
            p0[w0]     = acc[i][j][0] + bval;
            p1[w0]     = acc[i][j][1] + bval;
            p0[w0 + 8] = acc[i][j][2] + bval;
            p1[w0 + 8] = acc[i][j][3] + bval;
        }
    }
}

// ---------------------------------------------------------------------------
// Inputs (metadata order): x, core0, core1, core2, bias, [stride, pad]
// ---------------------------------------------------------------------------
extern "C" void kernel_launch(void* const* d_in, const int* in_sizes, int n_in,
                              void* d_out, int out_size) {
    const float* x     = (const float*)d_in[0];
    const float* core0 = (const float*)d_in[1];
    const float* core1 = (const float*)d_in[2];
    const float* core2 = (const float*)d_in[3];
    const float* bias  = (const float*)d_in[4];
    float* out = (float*)d_out;

    build_w_kernel<<<D_OUT, C_IN>>>(core0, core1, core2);
    prepack_x_kernel<<<dim3(32 * 4, IMG), 256>>>(x);

    const int smem_bytes = SM_TOTALW * 4;
    cudaFuncSetAttribute(conv_mma_kernel, cudaFuncAttributeMaxDynamicSharedMemorySize, smem_bytes);
    conv_mma_kernel<<<dim3(IMG / TH, 2, 32), 256, smem_bytes>>>(bias, out);
}

// round 9
// speedup vs baseline: 2.7649x; 1.1070x over previous
#include <cuda_runtime.h>
#include <cuda_fp16.h>
#include <cstdint>

// Problem constants
#define C_IN   128
#define D_OUT  256
#define IMG    64
#define R1     8
#define R2     4
#define TH     2           // output rows per CTA (M = 2*64 = 128)
#define ND     128         // output channels per CTA (N tile)
#define NG     12          // 4 c-chunks * 3 kh-groups

// SMEM word-layout (uint32 = half2 words)
#define SLAB_STRIDE  24                // 16 data words + 8 pad
#define SLAB_POS     264               // 4 rows * 66 cols (halo cols 0 and 65)
#define SLAB_WORDS   (SLAB_POS * SLAB_STRIDE)      // 6336 (single buffer)
#define B_TAP_WORDS  2048              // 2 ks * 128 d * 8 words
#define B_GRP_WORDS  (3 * B_TAP_WORDS)             // 6144 (3 kw taps)
#define SM_B         SLAB_WORDS
#define SM_TOTALW    (SM_B + 3 * B_GRP_WORDS)      // 24768 words = 99072 B

// fp16 weights, fragment-ready: word idx = (((tap*4+cc)*2+ks)*256 + d)*8 + wB
//   channel c (even) -> ks=(c&31)>>4, c16=c&15, wB=(c16&7)+(c16>>3); half2=(W[c],W[c+1])
__device__ uint32_t g_Wp[9 * 4 * 2 * 256 * 8];
// fp16 x, fragment-ready: word idx = (((n*4+cc)*64+h)*64+w)*16 + sw
//   sw -> channels: ks=sw>>3, wl=sw&7, c = cc*32 + ks*16 + 2*(wl>>1) + 8*(wl&1), pair (c,c+1)
__device__ uint32_t g_xh[32 * 4 * 64 * 64 * 16];   // 33.5 MB

__device__ __forceinline__ void mma_f16(float* d, const uint32_t* a, const uint32_t* b) {
    asm volatile(
        "mma.sync.aligned.m16n8k16.row.col.f32.f16.f16.f32 "
        "{%0,%1,%2,%3}, {%4,%5,%6,%7}, {%8,%9}, {%0,%1,%2,%3};"
        : "+f"(d[0]), "+f"(d[1]), "+f"(d[2]), "+f"(d[3])
        : "r"(a[0]), "r"(a[1]), "r"(a[2]), "r"(a[3]), "r"(b[0]), "r"(b[1]));
}
__device__ __forceinline__ void cp_async16(uint32_t saddr, const void* gptr) {
    asm volatile("cp.async.ca.shared.global [%0], [%1], 16;" :: "r"(saddr), "l"(gptr));
}

// ---------------------------------------------------------------------------
// Phase 1a: rebuild W (full fp32 math), pack fp16 pairs into g_Wp
// ---------------------------------------------------------------------------
__global__ void build_w_kernel(const float* __restrict__ core0,
                               const float* __restrict__ core1,
                               const float* __restrict__ core2) {
    const int d = blockIdx.x;
    const int t = threadIdx.x;           // 128 threads = channels
    __shared__ float M[R1 * 9];
    if (t < R1 * 9) {
        const int r = t / 9, kj = t % 9, kh = kj / 3, kw = kj % 3;
        float acc = 0.f;
        #pragma unroll
        for (int s = 0; s < R2; s++)
            acc += core1[((d * R1 + r) * 3 + kh) * R2 + s] * core2[(d * R2 + s) * 3 + kw];
        M[t] = acc;
    }
    __syncthreads();
    const int c = t;
    float a[R1];
    #pragma unroll
    for (int r = 0; r < R1; r++) a[r] = core0[(d * C_IN + c) * R1 + r];
    #pragma unroll
    for (int kj = 0; kj < 9; kj++) {
        float acc = 0.f;
        #pragma unroll
        for (int r = 0; r < R1; r++) acc += a[r] * M[r * 9 + kj];
        const float hiv = __shfl_down_sync(0xffffffffu, acc, 1);
        if (!(c & 1)) {
            const int cc = c >> 5, cl = c & 31;
            const int ks = cl >> 4, c16 = cl & 15;
            const int wB = (c16 & 7) + (c16 >> 3);
            __half2 h2 = __floats2half2_rn(acc, hiv);
            g_Wp[((((kj * 4 + cc) * 2 + ks) * 256) + d) * 8 + wB] =
                *reinterpret_cast<uint32_t*>(&h2);
        }
    }
}

// ---------------------------------------------------------------------------
// Phase 1b: convert x -> fp16 fragment-ready layout g_xh
// ---------------------------------------------------------------------------
__global__ __launch_bounds__(256)
void prepack_x_kernel(const float* __restrict__ x) {
    const int ncc = blockIdx.x;          // n*4+cc
    const int h   = blockIdx.y;
    const int n   = ncc >> 2;
    const int cc  = ncc & 3;
    const int tid = threadIdx.x;
    __shared__ float xs[32][65];

    for (int i = tid; i < 32 * 64; i += 256) {
        const int c = i >> 6, w = i & 63;
        xs[c][w] = x[((n * C_IN + cc * 32 + c) * IMG + h) * IMG + w];
    }
    __syncthreads();

    uint32_t* dst = g_xh + ((size_t)(ncc * 64 + h) * 64) * 16;
    for (int i = tid; i < 64 * 16; i += 256) {
        const int w = i >> 4, sw = i & 15;
        const int ks = sw >> 3, wl = sw & 7;
        const int c = ks * 16 + 2 * (wl >> 1) + 8 * (wl & 1);
        __half2 h2 = __floats2half2_rn(xs[c][w], xs[c + 1][w]);
        dst[w * 16 + sw] = *reinterpret_cast<uint32_t*>(&h2);
    }
}

// ---------------------------------------------------------------------------
// Phase 2: fp16 m16n8k16 implicit GEMM, kh-group pipeline.
// CTA: M=128 (2 rows x 64 cols) x N=128. 8 warps = 2(M-row) x 4(N); warp 64x32.
// Loop: 12 groups (cc 0..3 x kh 0..2); each group = 3 kw taps x 2 ksteps(K=16).
// B staged per-group (3 taps), triple-buffered, prefetch depth 2.
// Slab single-buffered, restaged in place at the 3 cc boundaries.
// One __syncthreads + one wait_group per GROUP (12 total).
// ---------------------------------------------------------------------------
__global__ __launch_bounds__(256, 2)
void conv_mma_kernel(const float* __restrict__ bias, float* __restrict__ out) {
    extern __shared__ uint32_t smw[];
    uint32_t* const slab = smw;
    const int tid = threadIdx.x;
    const int wid = tid >> 5;
    const int lane = tid & 31;
    const int g = lane >> 2;
    const int q = lane & 3;
    const int warp_m = wid & 1;
    const int warp_n = wid >> 1;
    const int ny = blockIdx.y;
    const int n  = blockIdx.z;
    const int h0 = blockIdx.x * TH;

    uint32_t smem_base;
    asm("{ .reg .u64 t; cvta.to.shared.u64 t, %1; cvt.u32.u64 %0, t; }"
        : "=r"(smem_base) : "l"((void*)smw));

    float acc[4][4][4];
    #pragma unroll
    for (int i = 0; i < 4; i++)
        #pragma unroll
        for (int j = 0; j < 4; j++)
            #pragma unroll
            for (int k = 0; k < 4; k++) acc[i][j][k] = 0.f;

    auto issue_slab = [&](int cc) {
        const uint32_t* gsrc = g_xh + ((size_t)(n * 4 + cc) * 64) * 64 * 16;
        #pragma unroll
        for (int t = 0; t < 4; t++) {
            const int i = tid + t * 256;      // 0..1023
            const int r = i >> 8, rem = i & 255;
            const int w = rem >> 2, cq = rem & 3;
            const int h = h0 - 1 + r;
            if ((unsigned)h < (unsigned)IMG)
                cp_async16(smem_base + (((r * 66 + 1 + w) * SLAB_STRIDE) + cq * 4) * 4,
                           gsrc + ((size_t)h * 64 + w) * 16 + cq * 4);
        }
    };
    auto issue_Bgrp = [&](int gi) {
        const int cc = gi / 3, kh = gi % 3, buf = gi % 3;
        const uint32_t sbase = smem_base + (SM_B + buf * B_GRP_WORDS) * 4;
        #pragma unroll
        for (int t = 0; t < 6; t++) {
            const int i = tid + t * 256;      // 0..1535
            const int t3 = i >> 9, rem = i & 511;
            const int ks = rem >> 8, ci = rem & 255;
            const uint32_t* gsrc =
                g_Wp + (size_t)((3 * kh + t3) * 4 + cc) * 4096 + ny * 1024;
            cp_async16(sbase + (t3 * 2048 + ks * 1024 + ci * 4) * 4,
                       gsrc + ks * 2048 + ci * 4);
        }
    };

    // ---- prologue: zero slab (halo stays zero), stage slab(0), B(0), B(1) ----
    for (int i = tid; i < SLAB_WORDS; i += 256) smw[i] = 0;
    __syncthreads();
    issue_slab(0);
    issue_Bgrp(0);
    asm volatile("cp.async.commit_group;" ::: "memory");
    issue_Bgrp(1);
    asm volatile("cp.async.commit_group;" ::: "memory");

    for (int gi = 0; gi < NG; gi++) {
        const int cc = gi / 3;
        const int kh = gi % 3;

        asm volatile("cp.async.wait_group 1;" ::: "memory");
        __syncthreads();
        if (gi > 0 && kh == 0) {
            // cc boundary: restage slab in place (all warps past the sync)
            issue_slab(cc);
            asm volatile("cp.async.commit_group;" ::: "memory");
            asm volatile("cp.async.wait_group 0;" ::: "memory");
            __syncthreads();
        }
        if (gi + 2 < NG) issue_Bgrp(gi + 2);
        asm volatile("cp.async.commit_group;" ::: "memory");

        const uint32_t* const Bg = smw + SM_B + (gi % 3) * B_GRP_WORDS;

        // ---- compute: 3 kw taps x 2 ksteps ----
        #pragma unroll
        for (int kw = 0; kw < 3; kw++) {
            const int posA = (warp_m + kh) * 66 + kw + g;
            #pragma unroll
            for (int ks = 0; ks < 2; ks++) {
                uint32_t a[4][4];
                #pragma unroll
                for (int i = 0; i < 4; i++) {
                    const int w0 = (posA + i * 16) * SLAB_STRIDE + ks * 8 + 2 * q;
                    const uint2 lo = *(const uint2*)(slab + w0);
                    const uint2 hi = *(const uint2*)(slab + w0 + 8 * SLAB_STRIDE);
                    a[i][0] = lo.x; a[i][1] = hi.x;
                    a[i][2] = lo.y; a[i][3] = hi.y;
                }
                uint32_t b[4][2];
                const uint32_t* Brow =
                    Bg + kw * 2048 + ks * 1024 + (warp_n * 32 + g) * 8 + 2 * q;
                #pragma unroll
                for (int j = 0; j < 4; j++) {
                    const uint2 bb = *(const uint2*)(Brow + j * 64);
                    b[j][0] = bb.x; b[j][1] = bb.y;
                }
                #pragma unroll
                for (int i = 0; i < 4; i++)
                    #pragma unroll
                    for (int j = 0; j < 4; j++)
                        mma_f16(acc[i][j], a[i], b[j]);
            }
        }
    }

    // ---- epilogue: acc -> out[n][d][h][w] + bias ----
    const float bval = bias[0];
    const int h = h0 + warp_m;
    #pragma unroll
    for (int i = 0; i < 4; i++) {
        const int w0 = i * 16 + g;
        #pragma unroll
        for (int j = 0; j < 4; j++) {
            const int d = ny * ND + warp_n * 32 + j * 8 + 2 * q;
            float* p0 = out + (((size_t)n * D_OUT + d) * IMG + h) * IMG;
            float* p1 = p0 + (size_t)IMG * IMG;       // d+1
            p0[w0]     = acc[i][j][0] + bval;
            p1[w0]     = acc[i][j][1] + bval;
            p0[w0 + 8] = acc[i][j][2] + bval;
            p1[w0 + 8] = acc[i][j][3] + bval;
        }
    }
}

// ---------------------------------------------------------------------------
// Inputs (metadata order): x, core0, core1, core2, bias, [stride, pad]
// ---------------------------------------------------------------------------
extern "C" void kernel_launch(void* const* d_in, const int* in_sizes, int n_in,
                              void* d_out, int out_size) {
    const float* x     = (const float*)d_in[0];
    const float* core0 = (const float*)d_in[1];
    const float* core1 = (const float*)d_in[2];
    const float* core2 = (const float*)d_in[3];
    const float* bias  = (const float*)d_in[4];
    float* out = (float*)d_out;

    build_w_kernel<<<D_OUT, C_IN>>>(core0, core1, core2);
    prepack_x_kernel<<<dim3(32 * 4, IMG), 256>>>(x);

    const int smem_bytes = SM_TOTALW * 4;
    cudaFuncSetAttribute(conv_mma_kernel, cudaFuncAttributeMaxDynamicSharedMemorySize, smem_bytes);
    conv_mma_kernel<<<dim3(IMG / TH, 2, 32), 256, smem_bytes>>>(bias, out);
}